// round 1
// baseline (speedup 1.0000x reference)
#include <cuda_runtime.h>

#define H_IMG 512
#define W_IMG 512
#define NMAX  2048
#define TILE  16
#define CHUNK 256

#define TWO_PI_F        6.28318530717958647692f
#define LOG2E_F         1.44269504088896340736f
#define LOG2_ALPHA_MIN  -7.99435344f   /* log2(1/255) */
#define ALPHA_MAX_F     0.999f

// Per-gaussian precomputed parameters (allocation-free device globals)
__device__ float4 g_P0[NMAX];  // mx, my, A(=0.5*c0), B(=0.5*c2)
__device__ float4 g_P1[NMAX];  // C(=c1), L(=log2(op)), fr, fg
__device__ float2 g_P2[NMAX];  // fb, r2 (cull radius^2; <0 => never contributes)

__global__ void prep_kernel(const float* __restrict__ xyz,
                            const float* __restrict__ scaling,
                            const float* __restrict__ rot,
                            const float* __restrict__ feat,
                            const float* __restrict__ opac,
                            int N)
{
    int i = blockIdx.x * blockDim.x + threadIdx.x;
    if (i >= N) return;

    float theta = (1.0f / (1.0f + expf(-rot[i]))) * TWO_PI_F;
    float s0 = fabsf(scaling[2*i + 0]); s0 *= s0;
    float s1 = fabsf(scaling[2*i + 1]); s1 *= s1;
    float cs = cosf(theta);
    float sn = sinf(theta);

    float a = cs*cs*s0 + sn*sn*s1;
    float b = cs*sn*(s0 - s1);
    float c = sn*sn*s0 + cs*cs*s1;
    float inv_det = 1.0f / (a*c - b*b);
    float c0 =  c * inv_det;
    float c1 = -b * inv_det;
    float c2 =  a * inv_det;

    float mx = 0.5f * ((xyz[2*i + 0] + 1.0f) * (float)W_IMG - 1.0f);
    float my = 0.5f * ((xyz[2*i + 1] + 1.0f) * (float)H_IMG - 1.0f);

    float op = opac[i];
    float L  = log2f(op);                 // alpha = 2^(L - sigma*log2e)
    float lnthr = logf(op * 255.0f);      // contributes iff sigma <= lnthr
    float smax  = fmaxf(s0, s1);          // = lambda_max(Sigma)
    // sigma >= 0.5*dist^2/smax  (exact conservative bound) => keep iff dist^2 <= 2*smax*lnthr
    float r2 = (lnthr > 0.0f) ? (2.0f * smax * lnthr) : -1.0f;

    g_P0[i] = make_float4(mx, my, 0.5f * c0, 0.5f * c2);
    g_P1[i] = make_float4(c1, L, feat[3*i + 0], feat[3*i + 1]);
    g_P2[i] = make_float2(feat[3*i + 2], r2);
}

__global__ __launch_bounds__(256, 4)
void render_kernel(float* __restrict__ out, int N)
{
    __shared__ float4 sP0[CHUNK];
    __shared__ float4 sP1[CHUNK];
    __shared__ float2 sP2[CHUNK];
    __shared__ int    s_cnt;

    const int tid  = threadIdx.x;
    const int lane = tid & 31;
    const int tx   = tid & (TILE - 1);
    const int ty   = tid >> 4;

    const int px = blockIdx.x * TILE + tx;
    const int py = blockIdx.y * TILE + ty;
    const float fx = (float)px;
    const float fy = (float)py;

    const float tx0 = (float)(blockIdx.x * TILE);
    const float tx1 = tx0 + (float)(TILE - 1);
    const float ty0 = (float)(blockIdx.y * TILE);
    const float ty1 = ty0 + (float)(TILE - 1);

    float accr = 0.0f, accg = 0.0f, accb = 0.0f;

    for (int base = 0; base < N; base += CHUNK) {
        int gi = base + tid;
        bool keep = false;
        float4 P0, P1; float2 P2;
        if (gi < N) {
            P0 = g_P0[gi];
            P1 = g_P1[gi];
            P2 = g_P2[gi];
            float dxb = fmaxf(0.0f, fmaxf(tx0 - P0.x, P0.x - tx1));
            float dyb = fmaxf(0.0f, fmaxf(ty0 - P0.y, P0.y - ty1));
            keep = (dxb*dxb + dyb*dyb) <= P2.y;
        }

        __syncthreads();               // previous chunk fully consumed
        if (tid == 0) s_cnt = 0;
        __syncthreads();               // reset visible

        unsigned mask = __ballot_sync(0xffffffffu, keep);
        int wcnt = __popc(mask);
        int wbase = 0;
        if (lane == 0 && wcnt) wbase = atomicAdd(&s_cnt, wcnt);
        wbase = __shfl_sync(0xffffffffu, wbase, 0);
        if (keep) {
            int pos = wbase + __popc(mask & ((1u << lane) - 1u));
            sP0[pos] = P0;
            sP1[pos] = P1;
            sP2[pos] = P2;
        }
        __syncthreads();               // compaction done
        int cnt = s_cnt;

        for (int j = 0; j < cnt; ++j) {
            float4 Q0 = sP0[j];
            float4 Q1 = sP1[j];
            float2 Q2 = sP2[j];
            float dx = fx - Q0.x;
            float dy = fy - Q0.y;
            // sigma = A*dx^2 + B*dy^2 + C*dx*dy
            float t     = fmaf(Q1.x, dy, Q0.z * dx);   // C*dy + A*dx
            float sigma = fmaf(Q0.w * dy, dy, t * dx); // B*dy^2 + dx*(...)
            // alpha = op * exp(-sigma) = 2^(L - sigma*log2e)
            float arg = fmaf(sigma, -LOG2E_F, Q1.y);
            float alpha;
            asm("ex2.approx.ftz.f32 %0, %1;" : "=f"(alpha) : "f"(arg));
            alpha = fminf(alpha, ALPHA_MAX_F);
            // alpha_raw < 1/255  <=>  arg < log2(1/255)   (min with 0.999 doesn't affect)
            if (arg >= LOG2_ALPHA_MIN) {
                accr = fmaf(alpha, Q1.z, accr);
                accg = fmaf(alpha, Q1.w, accg);
                accb = fmaf(alpha, Q2.x, accb);
            }
        }
    }

    // out layout: [1, 3, H, W]
    out[(0 * H_IMG + py) * W_IMG + px] = fminf(fmaxf(accr, 0.0f), 1.0f);
    out[(1 * H_IMG + py) * W_IMG + px] = fminf(fmaxf(accg, 0.0f), 1.0f);
    out[(2 * H_IMG + py) * W_IMG + px] = fminf(fmaxf(accb, 0.0f), 1.0f);
}

extern "C" void kernel_launch(void* const* d_in, const int* in_sizes, int n_in,
                              void* d_out, int out_size)
{
    const float* xyz     = (const float*)d_in[0];
    const float* scaling = (const float*)d_in[1];
    const float* rot     = (const float*)d_in[2];
    const float* feat    = (const float*)d_in[3];
    const float* opac    = (const float*)d_in[4];
    float* out = (float*)d_out;

    int N = in_sizes[0] / 2;
    if (N > NMAX) N = NMAX;

    prep_kernel<<<(N + 255) / 256, 256>>>(xyz, scaling, rot, feat, opac, N);

    dim3 grid(W_IMG / TILE, H_IMG / TILE);
    render_kernel<<<grid, 256>>>(out, N);
}